// round 5
// baseline (speedup 1.0000x reference)
#include <cuda_runtime.h>

#define BATCH 4096
#define HEADS 6
#define NROW  64
#define KDIM  64
#define DDIM  30
#define ROWS  (BATCH*NROW)   // 262144 reduced rows per head

// ---- global scratch (no allocations allowed) ----
__device__ unsigned g_amin[HEADS*KDIM];
__device__ unsigned g_amax[HEADS*KDIM];
__device__ unsigned g_bmin[HEADS*DDIM];
__device__ unsigned g_bmax[HEADS*DDIM];

// order-preserving float <-> uint map (works for mixed signs)
static __device__ __forceinline__ unsigned fkey(float f){
    unsigned u = __float_as_uint(f);
    return u ^ ((u & 0x80000000u) ? 0xFFFFFFFFu : 0x80000000u);
}
static __device__ __forceinline__ float funkey(unsigned k){
    unsigned u = (k & 0x80000000u) ? (k ^ 0x80000000u) : ~k;
    return __uint_as_float(u);
}

__global__ void init_minmax_kernel(){
    int i = blockIdx.x*blockDim.x + threadIdx.x;
    if (i < HEADS*KDIM){ g_amin[i] = 0xFFFFFFFFu; g_amax[i] = 0u; }
    if (i < HEADS*DDIM){ g_bmin[i] = 0xFFFFFFFFu; g_bmax[i] = 0u; }
}

// ---- min/max over axes (0,2) for A: per (h,k) channel, float4 loads ----
#define RA_BLOCKS 512
__global__ __launch_bounds__(512) void reduce_a_kernel(const float* __restrict__ A){
    const int h  = blockIdx.y;
    const int tx = threadIdx.x;        // 0..15 -> channels 4tx..4tx+3
    const int ty = threadIdx.y;        // 0..31
    const int rowsPer = ROWS / RA_BLOCKS;   // 512
    const int r0 = blockIdx.x * rowsPer;
    float4 mn = make_float4( 3.402823466e38f,  3.402823466e38f,  3.402823466e38f,  3.402823466e38f);
    float4 mx = make_float4(-3.402823466e38f, -3.402823466e38f, -3.402823466e38f, -3.402823466e38f);
    #pragma unroll 4
    for (int r = r0 + ty; r < r0 + rowsPer; r += 32){
        int b = r >> 6, n = r & 63;
        float4 v = *(const float4*)&A[(b*HEADS + h)*(NROW*KDIM) + n*KDIM + 4*tx];
        mn.x = fminf(mn.x, v.x); mx.x = fmaxf(mx.x, v.x);
        mn.y = fminf(mn.y, v.y); mx.y = fmaxf(mx.y, v.y);
        mn.z = fminf(mn.z, v.z); mx.z = fmaxf(mx.z, v.z);
        mn.w = fminf(mn.w, v.w); mx.w = fmaxf(mx.w, v.w);
    }
    __shared__ float4 sMn[32][16], sMx[32][16];
    sMn[ty][tx] = mn; sMx[ty][tx] = mx;
    __syncthreads();
    if (ty == 0){
        #pragma unroll 8
        for (int j = 1; j < 32; j++){
            float4 a = sMn[j][tx], b = sMx[j][tx];
            mn.x = fminf(mn.x, a.x); mx.x = fmaxf(mx.x, b.x);
            mn.y = fminf(mn.y, a.y); mx.y = fmaxf(mx.y, b.y);
            mn.z = fminf(mn.z, a.z); mx.z = fmaxf(mx.z, b.z);
            mn.w = fminf(mn.w, a.w); mx.w = fmaxf(mx.w, b.w);
        }
        int c = h*KDIM + 4*tx;
        atomicMin(&g_amin[c+0], fkey(mn.x)); atomicMax(&g_amax[c+0], fkey(mx.x));
        atomicMin(&g_amin[c+1], fkey(mn.y)); atomicMax(&g_amax[c+1], fkey(mx.y));
        atomicMin(&g_amin[c+2], fkey(mn.z)); atomicMax(&g_amax[c+2], fkey(mx.z));
        atomicMin(&g_amin[c+3], fkey(mn.w)); atomicMax(&g_amax[c+3], fkey(mx.w));
    }
}

// ---- min/max over axes (0,2) for B: per (h,d) channel ----
#define RB_BLOCKS 256
__global__ __launch_bounds__(512) void reduce_b_kernel(const float* __restrict__ B){
    const int h  = blockIdx.y;
    const int d  = threadIdx.x;        // 0..31, active < 30
    const int ty = threadIdx.y;        // 0..15
    const int rowsPer = ROWS / RB_BLOCKS;   // 1024
    const int r0 = blockIdx.x * rowsPer;
    float mn = 3.402823466e38f, mx = -3.402823466e38f;
    if (d < DDIM){
        #pragma unroll 4
        for (int r = r0 + ty; r < r0 + rowsPer; r += 16){
            int b = r >> 6, kk = r & 63;
            float v = B[(b*HEADS + h)*(KDIM*DDIM) + kk*DDIM + d];
            mn = fminf(mn, v); mx = fmaxf(mx, v);
        }
    }
    __shared__ float sMn[16][32], sMx[16][32];
    sMn[ty][d] = mn; sMx[ty][d] = mx;
    __syncthreads();
    if (ty == 0 && d < DDIM){
        #pragma unroll
        for (int j = 1; j < 16; j++){ mn = fminf(mn, sMn[j][d]); mx = fmaxf(mx, sMx[j][d]); }
        atomicMin(&g_bmin[h*DDIM + d], fkey(mn));
        atomicMax(&g_bmax[h*DDIM + d], fkey(mx));
    }
}

// packed fp32x2 FMA (FFMA2): not emitted by ptxas from C++, PTX-only
#define FFMA2(acc, av, bv) \
    asm("fma.rn.f32x2 %0, %1, %2, %0;" : "+l"(acc) : "l"(av), "l"(bv))

// ---- fused fake-quant + matmul: one CTA (64 thr) per (b,h) tile ----
// 4 rows x 8 cols per thread. ASTRIDE=68 -> 272B rows, 16B-aligned -> LDS.128 A frags.
#define ASTRIDE 68
__global__ __launch_bounds__(64) void qmm_kernel(const float* __restrict__ A,
                                                 const float* __restrict__ B,
                                                 const int*   __restrict__ nbits,
                                                 float*       __restrict__ C){
    __shared__ __align__(16) float As[KDIM][ASTRIDE];  // [k][n]; reused as C staging
    __shared__ __align__(16) float Bs[KDIM][32];       // [k][d], 128B rows
    __shared__ float sdb[32], szb[32], sib[32];

    const int bh = blockIdx.x;             // b*HEADS + h
    const int h  = bh % HEADS;
    const int t  = threadIdx.x;            // 0..63
    const float levels = (float)((1 << nbits[0]) - 1);

    // A channel k=t params -> registers (exact IEEE division, matches jnp)
    float amn = funkey(g_amin[h*KDIM + t]);
    float amx = funkey(g_amax[h*KDIM + t]);
    float da  = fmaxf((amx - amn) / levels, 1e-8f);
    float za  = rintf(-amn / da);
    float ia  = 1.0f / da;

    if (t < DDIM){
        float bmn = funkey(g_bmin[h*DDIM + t]);
        float bmx = funkey(g_bmax[h*DDIM + t]);
        float db  = fmaxf((bmx - bmn) / levels, 1e-8f);
        sdb[t] = db;
        szb[t] = rintf(-bmn / db);
        sib[t] = 1.0f / db;
    }
    Bs[t][30] = 0.f; Bs[t][31] = 0.f;      // zero pad columns
    __syncthreads();

    // load + fake-quant A tile (64x64): thread owns channel k=t, all rows
    const float* Ab = A + bh * (NROW*KDIM);
    #pragma unroll 8
    for (int n = 0; n < NROW; n++){
        float v = Ab[n*KDIM + t];
        float q = rintf(v * ia) + za;
        q = fminf(fmaxf(q, 0.f), levels);
        As[t][n] = (q - za) * da;
    }
    // load + fake-quant B tile (64x30)
    const float* Bb = B + bh * (KDIM*DDIM);
    #pragma unroll 6
    for (int e = t; e < KDIM*DDIM; e += 64){
        int kk = e / DDIM;
        int d  = e - kk*DDIM;
        float v = Bb[e];
        float q = rintf(v * sib[d]) + szb[d];
        q = fminf(fmaxf(q, 0.f), levels);
        Bs[kk][d] = (q - szb[d]) * sdb[d];
    }
    __syncthreads();

    // compute: 4 rows x 8 cols per thread; 16 row-groups x 4 col-groups
    const int rg = t & 15;                 // rows 4rg..4rg+3
    const int cg = t >> 4;                 // cols cg*8..+7
    unsigned long long acc[4][4];
    #pragma unroll
    for (int i = 0; i < 4; i++)
        #pragma unroll
        for (int j = 0; j < 4; j++)
            acc[i][j] = 0ULL;

    const float* arow = &As[0][4*rg];
    const float* brow = &Bs[0][cg*8];

    // distance-1 software pipeline
    float4 a_n = *(const float4*)arow;
    ulonglong2 b01_n = *(const ulonglong2*)brow;
    ulonglong2 b23_n = *(const ulonglong2*)(brow + 4);

    #pragma unroll 8
    for (int kk = 0; kk < KDIM; kk++){
        float4 a = a_n;
        ulonglong2 b01 = b01_n, b23 = b23_n;
        if (kk < KDIM-1){
            arow += ASTRIDE; brow += 32;
            a_n   = *(const float4*)arow;          // LDS.128, 16B-aligned
            b01_n = *(const ulonglong2*)brow;
            b23_n = *(const ulonglong2*)(brow + 4);
        }
        unsigned long long a0d, a1d, a2d, a3d;
        asm("mov.b64 %0, {%1, %1};" : "=l"(a0d) : "f"(a.x));
        asm("mov.b64 %0, {%1, %1};" : "=l"(a1d) : "f"(a.y));
        asm("mov.b64 %0, {%1, %1};" : "=l"(a2d) : "f"(a.z));
        asm("mov.b64 %0, {%1, %1};" : "=l"(a3d) : "f"(a.w));
        FFMA2(acc[0][0], a0d, b01.x); FFMA2(acc[0][1], a0d, b01.y);
        FFMA2(acc[0][2], a0d, b23.x); FFMA2(acc[0][3], a0d, b23.y);
        FFMA2(acc[1][0], a1d, b01.x); FFMA2(acc[1][1], a1d, b01.y);
        FFMA2(acc[1][2], a1d, b23.x); FFMA2(acc[1][3], a1d, b23.y);
        FFMA2(acc[2][0], a2d, b01.x); FFMA2(acc[2][1], a2d, b01.y);
        FFMA2(acc[2][2], a2d, b23.x); FFMA2(acc[2][3], a2d, b23.y);
        FFMA2(acc[3][0], a3d, b01.x); FFMA2(acc[3][1], a3d, b01.y);
        FFMA2(acc[3][2], a3d, b23.x); FFMA2(acc[3][3], a3d, b23.y);
    }

    // ---- epilogue: stage C tile in smem (reuse As), then coalesced STG.128 ----
    __syncthreads();                       // all As reads done before overwrite
    float* Cs = &As[0][0];                 // 64*30 = 1920 floats
    #pragma unroll
    for (int i = 0; i < 4; i++){
        int n = 4*rg + i;
        #pragma unroll
        for (int j = 0; j < 4; j++){
            int d = cg*8 + 2*j;
            if (d < DDIM){                 // drops pad pair (d=30) for cg=3
                *(unsigned long long*)(Cs + n*DDIM + d) = acc[i][j];
            }
        }
    }
    __syncthreads();
    float* Cb = C + bh * (NROW*DDIM);
    #pragma unroll
    for (int i4 = t; i4 < (NROW*DDIM)/4; i4 += 64){   // 480 float4, coalesced
        *(float4*)(Cb + 4*i4) = *(const float4*)(Cs + 4*i4);
    }
}

extern "C" void kernel_launch(void* const* d_in, const int* in_sizes, int n_in,
                              void* d_out, int out_size){
    const float* A  = (const float*)d_in[0];
    const float* B  = (const float*)d_in[1];
    const int*   nb = (const int*)d_in[2];
    float*       C  = (float*)d_out;

    init_minmax_kernel<<<2, 256>>>();
    reduce_a_kernel<<<dim3(RA_BLOCKS, HEADS), dim3(16, 32)>>>(A);
    reduce_b_kernel<<<dim3(RB_BLOCKS, HEADS), dim3(32, 16)>>>(B);
    qmm_kernel<<<BATCH*HEADS, 64>>>(A, B, nb, C);
}

// round 6
// speedup vs baseline: 1.3662x; 1.3662x over previous
#include <cuda_runtime.h>

#define BATCH 4096
#define HEADS 6
#define NROW  64
#define KDIM  64
#define DDIM  30
#define ROWS  (BATCH*NROW)   // 262144 reduced rows per head

// ---- global scratch (no allocations allowed) ----
__device__ unsigned g_amin[HEADS*KDIM];
__device__ unsigned g_amax[HEADS*KDIM];
__device__ unsigned g_bmin[HEADS*DDIM];
__device__ unsigned g_bmax[HEADS*DDIM];

// order-preserving float <-> uint map (works for mixed signs)
static __device__ __forceinline__ unsigned fkey(float f){
    unsigned u = __float_as_uint(f);
    return u ^ ((u & 0x80000000u) ? 0xFFFFFFFFu : 0x80000000u);
}
static __device__ __forceinline__ float funkey(unsigned k){
    unsigned u = (k & 0x80000000u) ? (k ^ 0x80000000u) : ~k;
    return __uint_as_float(u);
}

__global__ void init_minmax_kernel(){
    int i = blockIdx.x*blockDim.x + threadIdx.x;
    if (i < HEADS*KDIM){ g_amin[i] = 0xFFFFFFFFu; g_amax[i] = 0u; }
    if (i < HEADS*DDIM){ g_bmin[i] = 0xFFFFFFFFu; g_bmax[i] = 0u; }
}

// ---- min/max over axes (0,2) for A: per (h,k) channel, float4 loads ----
#define RA_BLOCKS 512
__global__ __launch_bounds__(512) void reduce_a_kernel(const float* __restrict__ A){
    const int h  = blockIdx.y;
    const int tx = threadIdx.x;        // 0..15 -> channels 4tx..4tx+3
    const int ty = threadIdx.y;        // 0..31
    const int rowsPer = ROWS / RA_BLOCKS;   // 512
    const int r0 = blockIdx.x * rowsPer;
    float4 mn = make_float4( 3.402823466e38f,  3.402823466e38f,  3.402823466e38f,  3.402823466e38f);
    float4 mx = make_float4(-3.402823466e38f, -3.402823466e38f, -3.402823466e38f, -3.402823466e38f);
    #pragma unroll 4
    for (int r = r0 + ty; r < r0 + rowsPer; r += 32){
        int b = r >> 6, n = r & 63;
        float4 v = *(const float4*)&A[(b*HEADS + h)*(NROW*KDIM) + n*KDIM + 4*tx];
        mn.x = fminf(mn.x, v.x); mx.x = fmaxf(mx.x, v.x);
        mn.y = fminf(mn.y, v.y); mx.y = fmaxf(mx.y, v.y);
        mn.z = fminf(mn.z, v.z); mx.z = fmaxf(mx.z, v.z);
        mn.w = fminf(mn.w, v.w); mx.w = fmaxf(mx.w, v.w);
    }
    __shared__ float4 sMn[32][16], sMx[32][16];
    sMn[ty][tx] = mn; sMx[ty][tx] = mx;
    __syncthreads();
    if (ty == 0){
        #pragma unroll 8
        for (int j = 1; j < 32; j++){
            float4 a = sMn[j][tx], b = sMx[j][tx];
            mn.x = fminf(mn.x, a.x); mx.x = fmaxf(mx.x, b.x);
            mn.y = fminf(mn.y, a.y); mx.y = fmaxf(mx.y, b.y);
            mn.z = fminf(mn.z, a.z); mx.z = fmaxf(mx.z, b.z);
            mn.w = fminf(mn.w, a.w); mx.w = fmaxf(mx.w, b.w);
        }
        int c = h*KDIM + 4*tx;
        atomicMin(&g_amin[c+0], fkey(mn.x)); atomicMax(&g_amax[c+0], fkey(mx.x));
        atomicMin(&g_amin[c+1], fkey(mn.y)); atomicMax(&g_amax[c+1], fkey(mx.y));
        atomicMin(&g_amin[c+2], fkey(mn.z)); atomicMax(&g_amax[c+2], fkey(mx.z));
        atomicMin(&g_amin[c+3], fkey(mn.w)); atomicMax(&g_amax[c+3], fkey(mx.w));
    }
}

// ---- min/max over axes (0,2) for B: per (h,d) channel ----
#define RB_BLOCKS 256
__global__ __launch_bounds__(512) void reduce_b_kernel(const float* __restrict__ B){
    const int h  = blockIdx.y;
    const int d  = threadIdx.x;        // 0..31, active < 30
    const int ty = threadIdx.y;        // 0..15
    const int rowsPer = ROWS / RB_BLOCKS;   // 1024
    const int r0 = blockIdx.x * rowsPer;
    float mn = 3.402823466e38f, mx = -3.402823466e38f;
    if (d < DDIM){
        #pragma unroll 4
        for (int r = r0 + ty; r < r0 + rowsPer; r += 16){
            int b = r >> 6, kk = r & 63;
            float v = B[(b*HEADS + h)*(KDIM*DDIM) + kk*DDIM + d];
            mn = fminf(mn, v); mx = fmaxf(mx, v);
        }
    }
    __shared__ float sMn[16][32], sMx[16][32];
    sMn[ty][d] = mn; sMx[ty][d] = mx;
    __syncthreads();
    if (ty == 0 && d < DDIM){
        #pragma unroll
        for (int j = 1; j < 16; j++){ mn = fminf(mn, sMn[j][d]); mx = fmaxf(mx, sMx[j][d]); }
        atomicMin(&g_bmin[h*DDIM + d], fkey(mn));
        atomicMax(&g_bmax[h*DDIM + d], fkey(mx));
    }
}

// packed fp32x2 FMA (FFMA2): not emitted by ptxas from C++, PTX-only
#define FFMA2(acc, av, bv) \
    asm("fma.rn.f32x2 %0, %1, %2, %0;" : "+l"(acc) : "l"(av), "l"(bv))

// ---- fused fake-quant + matmul: one CTA (128 thr) per (b,h) tile ----
// Thread tile 2 rows x 8 cols. Warp covers 32 rows x 16 cols:
//   lane&15 -> row group (2 rows), lane>>4 -> col group (8 cols)
//   warp&1  -> row half (32 rows), warp>>1 -> col half (16 cols)
// => A fragment LDS.64: 16 distinct 8B chunks, hi/lo half-warps dedup = 1 wavefront
// => B fragment LDS.128 x2: 2 distinct 16B chunks each = 1 wavefront each
#define ASTRIDE 66   // even -> 8B-aligned rows for LDS.64; 2-way-only STS conflicts
__global__ __launch_bounds__(128) void qmm_kernel(const float* __restrict__ A,
                                                  const float* __restrict__ B,
                                                  const int*   __restrict__ nbits,
                                                  float*       __restrict__ C){
    __shared__ __align__(16) float As[KDIM][ASTRIDE];  // [k][n]; reused as C staging
    __shared__ __align__(16) float Bs[KDIM][32];       // [k][d], 128B rows
    __shared__ float sdb[32], szb[32], sib[32];

    const int bh = blockIdx.x;             // b*HEADS + h
    const int h  = bh % HEADS;
    const int t  = threadIdx.x;            // 0..127
    const int k  = t & 63;                 // owned A channel for quant phase
    const int half = t >> 6;               // 0/1: row half for A quant
    const float levels = (float)((1 << nbits[0]) - 1);

    // A channel params (exact IEEE division, matches jnp)
    float amn = funkey(g_amin[h*KDIM + k]);
    float amx = funkey(g_amax[h*KDIM + k]);
    float da  = fmaxf((amx - amn) / levels, 1e-8f);
    float za  = rintf(-amn / da);
    float ia  = 1.0f / da;

    if (t < DDIM){
        float bmn = funkey(g_bmin[h*DDIM + t]);
        float bmx = funkey(g_bmax[h*DDIM + t]);
        float db  = fmaxf((bmx - bmn) / levels, 1e-8f);
        sdb[t] = db;
        szb[t] = rintf(-bmn / db);
        sib[t] = 1.0f / db;
    }
    if (t < 64){ Bs[t][30] = 0.f; Bs[t][31] = 0.f; }   // zero pad columns
    __syncthreads();

    // load + fake-quant A tile (64x64): thread owns channel k, half the rows
    const float* Ab = A + bh * (NROW*KDIM);
    #pragma unroll 8
    for (int nn = 0; nn < 32; nn++){
        int n = half*32 + nn;
        float v = Ab[n*KDIM + k];
        float q = rintf(v * ia) + za;
        q = fminf(fmaxf(q, 0.f), levels);
        As[k][n] = (q - za) * da;
    }
    // load + fake-quant B tile (64x30): fixed d per thread, march kk
    // (no integer div/mod; coalesced LDG; conflict-free STS)
    {
        const float* Bb = B + bh * (KDIM*DDIM);
        int d  = t & 31;
        int k0 = t >> 5;                   // 0..3
        if (d < DDIM){
            float db = sdb[d], zb = szb[d], ib = sib[d];
            #pragma unroll
            for (int i = 0; i < 16; i++){
                int kk = k0 + 4*i;
                float v = Bb[kk*DDIM + d];
                float q = rintf(v * ib) + zb;
                q = fminf(fmaxf(q, 0.f), levels);
                Bs[kk][d] = (q - zb) * db;
            }
        }
    }
    __syncthreads();

    // compute mapping: warp spans 32 rows x 16 cols
    const int lane  = t & 31;
    const int w     = t >> 5;
    const int rg    = lane & 15;           // rows 2*rg, 2*rg+1 within half
    const int cgl   = lane >> 4;           // col group within warp (0/1)
    const int roww  = w & 1;               // row half
    const int colw  = w >> 1;              // col half
    const int nbase = roww*32 + 2*rg;      // global row base
    const int dbase = colw*16 + cgl*8;     // global col base

    unsigned long long acc[2][4];
    #pragma unroll
    for (int i = 0; i < 2; i++)
        #pragma unroll
        for (int j = 0; j < 4; j++)
            acc[i][j] = 0ULL;

    const float* arow = &As[0][nbase];
    const float* brow = &Bs[0][dbase];

    // distance-1 software pipeline
    float2 a_n = *(const float2*)arow;
    ulonglong2 b01_n = *(const ulonglong2*)brow;
    ulonglong2 b23_n = *(const ulonglong2*)(brow + 4);

    #pragma unroll 8
    for (int kk = 0; kk < KDIM; kk++){
        float2 a = a_n;
        ulonglong2 b01 = b01_n, b23 = b23_n;
        if (kk < KDIM-1){
            arow += ASTRIDE; brow += 32;
            a_n   = *(const float2*)arow;
            b01_n = *(const ulonglong2*)brow;
            b23_n = *(const ulonglong2*)(brow + 4);
        }
        unsigned long long a0d, a1d;
        asm("mov.b64 %0, {%1, %1};" : "=l"(a0d) : "f"(a.x));
        asm("mov.b64 %0, {%1, %1};" : "=l"(a1d) : "f"(a.y));
        FFMA2(acc[0][0], a0d, b01.x); FFMA2(acc[0][1], a0d, b01.y);
        FFMA2(acc[0][2], a0d, b23.x); FFMA2(acc[0][3], a0d, b23.y);
        FFMA2(acc[1][0], a1d, b01.x); FFMA2(acc[1][1], a1d, b01.y);
        FFMA2(acc[1][2], a1d, b23.x); FFMA2(acc[1][3], a1d, b23.y);
    }

    // ---- epilogue: stage C tile in smem (reuse As), then coalesced STG.128 ----
    __syncthreads();                       // all As reads done before overwrite
    float* Cs = &As[0][0];                 // 64*30 = 1920 floats
    #pragma unroll
    for (int i = 0; i < 2; i++){
        int n = nbase + i;
        #pragma unroll
        for (int j = 0; j < 4; j++){
            int d = dbase + 2*j;
            if (d < DDIM){                 // drops pad pair d=30
                *(unsigned long long*)(Cs + n*DDIM + d) = acc[i][j];
            }
        }
    }
    __syncthreads();
    float* Cb = C + bh * (NROW*DDIM);
    #pragma unroll
    for (int i4 = t; i4 < (NROW*DDIM)/4; i4 += 128){   // 480 float4, coalesced
        *(float4*)(Cb + 4*i4) = *(const float4*)(Cs + 4*i4);
    }
}

extern "C" void kernel_launch(void* const* d_in, const int* in_sizes, int n_in,
                              void* d_out, int out_size){
    const float* A  = (const float*)d_in[0];
    const float* B  = (const float*)d_in[1];
    const int*   nb = (const int*)d_in[2];
    float*       C  = (float*)d_out;

    init_minmax_kernel<<<2, 256>>>();
    reduce_a_kernel<<<dim3(RA_BLOCKS, HEADS), dim3(16, 32)>>>(A);
    reduce_b_kernel<<<dim3(RB_BLOCKS, HEADS), dim3(32, 16)>>>(B);
    qmm_kernel<<<BATCH*HEADS, 128>>>(A, B, nb, C);
}